// round 14
// baseline (speedup 1.0000x reference)
#include <cuda_runtime.h>
#include <cuda_fp16.h>
#include <math.h>

#define H      256
#define BSZ    128
#define PPA    1024
#define LPA    128
#define NCOMBO 8192

// -------- scratch (no allocations allowed) --------
__device__ float4  g_F4[180 * (H / 4)];          // embed@Wd1 rows
#define G_F ((const float*)g_F4)
__device__ __half2 g_table_h2[NCOMBO * (H / 2)]; // fp16 silu table (4.2MB)
__device__ __half2 g_ligtab_h2[16 * (H / 2)];
__device__ float   g_MTf[H * 512];               // TRANSPOSED M, fp32: [h][k], k=512 (512KB)
__device__ float   g_cpart[4][H];                // const-vector partials (bd2 fold + ba1)
__device__ float   g_lmin[BSZ * 2 * LPA];        // partial min d2 (+|l|^2) per (batch,half,atom)
__device__ float   g_mean[2 * BSZ * H];          // [0,32768): protein sums, [32768,): ligand sums

__device__ __forceinline__ float silu_acc(float x) {
    return x / (1.0f + expf(-x));
}
// Polynomial sigma for tiny |x| (table pre-acts ~N(0,0.011)); exact fallback.
__device__ __forceinline__ float silu_poly(float x) {
    float x2 = x * x;
    float s = 0.5f + x * (0.25f + x2 * (-1.0f / 48.0f + x2 * (1.0f / 480.0f)));
    if (fabsf(x) > 0.25f) s = __fdividef(1.0f, 1.0f + __expf(-x));
    return x * s;
}

__device__ __forceinline__ const float* emb_src(int r, const float* Ee, const float* Ea,
                                                const float* Eb, const float* El) {
    if (r < 128) return Ee + r * H;
    if (r < 160) return Ea + (r - 128) * H;
    if (r < 162) return Eb + (r - 160) * H;
    if (r < 178) return El + (r - 162) * H;
    return Ee;  // dummy rows
}

// ============================================================================
// K1 — 109 blocks x 512: [0,45) embed GEMM -> g_F; [45,109) zero g_mean (+out)
// ============================================================================
__global__ void __launch_bounds__(512)
k_embed(const float* __restrict__ E_elem, const float* __restrict__ E_aa,
        const float* __restrict__ E_bb,   const float* __restrict__ E_lig,
        const float* __restrict__ Wd1,    float* __restrict__ out) {
    __shared__ float  sA[4][H];
    __shared__ float4 sRed[8][4][64];
    int blk = blockIdx.x, t = threadIdx.x;
    if (blk >= 45) {
        ((float2*)g_mean)[(blk - 45) * 512 + t] = make_float2(0.f, 0.f);
        if (blk == 45 && t < BSZ) out[t] = 0.f;
        return;
    }
    int r0 = blk * 4;
    for (int r = t >> 8; r < 4; r += 2)
        sA[r][t & 255] = emb_src(r0 + r, E_elem, E_aa, E_bb, E_lig)[t & 255];
    __syncthreads();
    int q = t >> 6, u = t & 63;
    float4 a0 = {0,0,0,0}, a1 = {0,0,0,0}, a2 = {0,0,0,0}, a3 = {0,0,0,0};
    const float* Wp = Wd1 + (q * 32) * H + 4 * u;
    const float* sa = &sA[0][q * 32];
    #pragma unroll 8
    for (int j = 0; j < 32; ++j) {
        float4 w = *(const float4*)(Wp + j * H);
        float s0 = sa[0 * H + j], s1 = sa[1 * H + j];
        float s2 = sa[2 * H + j], s3 = sa[3 * H + j];
        a0.x += s0 * w.x; a0.y += s0 * w.y; a0.z += s0 * w.z; a0.w += s0 * w.w;
        a1.x += s1 * w.x; a1.y += s1 * w.y; a1.z += s1 * w.z; a1.w += s1 * w.w;
        a2.x += s2 * w.x; a2.y += s2 * w.y; a2.z += s2 * w.z; a2.w += s2 * w.w;
        a3.x += s3 * w.x; a3.y += s3 * w.y; a3.z += s3 * w.z; a3.w += s3 * w.w;
    }
    sRed[q][0][u] = a0; sRed[q][1][u] = a1;
    sRed[q][2][u] = a2; sRed[q][3][u] = a3;
    __syncthreads();
    if (t < 256) {
        int r = t >> 6, u2 = t & 63;
        float4 f = sRed[0][r][u2];
        #pragma unroll
        for (int q2 = 1; q2 < 8; ++q2) {
            float4 g = sRed[q2][r][u2];
            f.x += g.x; f.y += g.y; f.z += g.z; f.w += g.w;
        }
        g_F4[(r0 + r) * (H / 4) + u2] = f;
    }
}

// ============================================================================
// K2 — 4492 blocks x 256 (long blocks first), unioned smem:
//   [0,128) M GEMM (writes TRANSPOSED fp32 MT); [128,132) const partials;
//   [132,388) distance; rest silu tables
// ============================================================================
__global__ void __launch_bounds__(256)
k_big(const float* __restrict__ Wd2, const float* __restrict__ Wa1,
      const float* __restrict__ bd2, const float* __restrict__ ba1,
      const float* __restrict__ bd1,
      const float* __restrict__ ppos, const float* __restrict__ lpos) {
    __shared__ union {
        struct { float sA[4][H]; float4 sRed[4][4][64]; float sFin[4][H]; } m;  // 24KB
        struct { float4 sp[512]; float dmin2[256]; } d;                          // 9KB
    } sh;
    int blk = blockIdx.x, t = threadIdx.x;

    if (blk < 128) {
        // ---------------- M GEMM -> transposed fp32 g_MTf ----------------
        int r0 = blk * 4;
        #pragma unroll
        for (int r = 0; r < 4; ++r)
            sh.m.sA[r][t] = Wd2[((r0 + r) & 255) * H + t];
        const float* W = Wa1 + ((r0 >> 8) * 256) * H;
        __syncthreads();
        int q = t >> 6, u = t & 63;
        float4 a0 = {0,0,0,0}, a1 = {0,0,0,0}, a2 = {0,0,0,0}, a3 = {0,0,0,0};
        const float* Wp = W + (q * 64) * H + 4 * u;
        const float* sa = &sh.m.sA[0][q * 64];
        #pragma unroll 8
        for (int j = 0; j < 64; ++j) {
            float4 w = *(const float4*)(Wp + j * H);
            float s0 = sa[0 * H + j], s1 = sa[1 * H + j];
            float s2 = sa[2 * H + j], s3 = sa[3 * H + j];
            a0.x += s0 * w.x; a0.y += s0 * w.y; a0.z += s0 * w.z; a0.w += s0 * w.w;
            a1.x += s1 * w.x; a1.y += s1 * w.y; a1.z += s1 * w.z; a1.w += s1 * w.w;
            a2.x += s2 * w.x; a2.y += s2 * w.y; a2.z += s2 * w.z; a2.w += s2 * w.w;
            a3.x += s3 * w.x; a3.y += s3 * w.y; a3.z += s3 * w.z; a3.w += s3 * w.w;
        }
        sh.m.sRed[q][0][u] = a0; sh.m.sRed[q][1][u] = a1;
        sh.m.sRed[q][2][u] = a2; sh.m.sRed[q][3][u] = a3;
        __syncthreads();
        {
            int r = t >> 6, u2 = t & 63;
            float4 f0 = sh.m.sRed[0][r][u2], f1 = sh.m.sRed[1][r][u2];
            float4 f2 = sh.m.sRed[2][r][u2], f3 = sh.m.sRed[3][r][u2];
            float4 f = make_float4(f0.x + f1.x + f2.x + f3.x,
                                   f0.y + f1.y + f2.y + f3.y,
                                   f0.z + f1.z + f2.z + f3.z,
                                   f0.w + f1.w + f2.w + f3.w);
            *(float4*)&sh.m.sFin[r][4 * u2] = f;
        }
        __syncthreads();
        {   // transposed write: one STG.128 per h (rows r0..r0+3 of column h)
            int h = t;
            float4 st = make_float4(sh.m.sFin[0][h], sh.m.sFin[1][h],
                                    sh.m.sFin[2][h], sh.m.sFin[3][h]);
            *(float4*)&g_MTf[h * 512 + r0] = st;
        }
    } else if (blk < 132) {
        // ---------------- const partials ----------------
        int qq = blk - 128;
        int j0 = qq * 64;
        float acc = (qq == 0) ? ba1[t] : 0.f;
        #pragma unroll 8
        for (int j = j0; j < j0 + 64; ++j) {
            float b = bd2[j];
            acc += b * (Wa1[j * H + t] + Wa1[(256 + j) * H + t]);
        }
        g_cpart[qq][t] = acc;
    } else if (blk < 388) {
        // ---------------- distance partial min ----------------
        int d = blk - 132;
        int b = d >> 1, half = d & 1;
        for (int j = t; j < 512; j += 256) {
            int i = b * PPA + half * 512 + j;
            float px = ppos[3 * i], py = ppos[3 * i + 1], pz = ppos[3 * i + 2];
            sh.d.sp[j] = make_float4(px, py, pz, px * px + py * py + pz * pz);
        }
        __syncthreads();
        int la = t & 127, jh = t >> 7;
        int li = b * LPA + la;
        float lx = lpos[3 * li], ly = lpos[3 * li + 1], lz = lpos[3 * li + 2];
        float ll = lx * lx + ly * ly + lz * lz;
        float nx = -2.f * lx, ny = -2.f * ly, nz = -2.f * lz;
        float b0 = 3.4e38f, b1 = 3.4e38f;
        int base = jh * 256;
        #pragma unroll 4
        for (int j = 0; j < 256; j += 2) {
            float4 p  = sh.d.sp[base + j];
            float4 q4 = sh.d.sp[base + j + 1];
            float d0 = fmaf(nx, p.x,  fmaf(ny, p.y,  fmaf(nz, p.z,  p.w)));
            float d1 = fmaf(nx, q4.x, fmaf(ny, q4.y, fmaf(nz, q4.z, q4.w)));
            b0 = fminf(b0, d0);
            b1 = fminf(b1, d1);
        }
        sh.d.dmin2[t] = fminf(b0, b1);
        __syncthreads();
        if (t < 128)
            g_lmin[d * LPA + t] = fminf(sh.d.dmin2[t], sh.d.dmin2[t + 128]) + ll;
    } else {
        // ---------------- silu tables ----------------
        int tb = blk - 388;
        int hp = t & 127;
        if (tb < NCOMBO / 2) {
            int c = 2 * tb + (t >> 7);
            int e = c >> 6, a = (c >> 1) & 31, bbn = c & 1;
            float2 fe = *(const float2*)&G_F[e * H + 2 * hp];
            float2 fa = *(const float2*)&G_F[(128 + a) * H + 2 * hp];
            float2 fb = *(const float2*)&G_F[(160 + bbn) * H + 2 * hp];
            float2 bd = *(const float2*)&bd1[2 * hp];
            g_table_h2[c * (H / 2) + hp] =
                __floats2half2_rn(silu_poly(fe.x + fa.x + fb.x + bd.x),
                                  silu_poly(fe.y + fa.y + fb.y + bd.y));
        } else {
            int c = 2 * (tb - NCOMBO / 2) + (t >> 7);
            float2 fl = *(const float2*)&G_F[(162 + c) * H + 2 * hp];
            float2 bd = *(const float2*)&bd1[2 * hp];
            g_ligtab_h2[c * (H / 2) + hp] =
                __floats2half2_rn(silu_poly(fl.x + bd.x), silu_poly(fl.y + bd.y));
        }
    }
}

// ============================================================================
// K3 — 512 blocks x 512 (4 blocks/batch, quarter each), uint2 gathers
// ============================================================================
__global__ void __launch_bounds__(512)
k_pool(const int* __restrict__ elem, const int* __restrict__ aa,
       const int* __restrict__ bb,   const int* __restrict__ ltype) {
    __shared__ int    sc[256];
    __shared__ int    scl[32];
    __shared__ float4 part[8][64];
    int d = blockIdx.x, t = threadIdx.x;
    int b = d >> 2, qtr = d & 3;
    int hq = t & 63, sl = t >> 6;        // h-quad, j-slice (8)
    const uint2* tab = (const uint2*)g_table_h2;
    const uint2* ltab = (const uint2*)g_ligtab_h2;

    if (t < 256) {
        int i = b * PPA + qtr * 256 + t;
        sc[t] = ((elem[i] << 6) | (aa[i] << 1) | bb[i]) << 6;
    } else if (t < 288) {
        int j = t - 256;
        scl[j] = ltype[b * LPA + qtr * 32 + j] << 6;
    }
    __syncthreads();

    {   // protein: 32 atoms per thread, 8B loads
        float2 A0 = {0,0}, B0 = {0,0}, A1 = {0,0}, B1 = {0,0};
        float2 A2 = {0,0}, B2 = {0,0}, A3 = {0,0}, B3 = {0,0};
        int jb = sl * 32;
        #pragma unroll 4
        for (int j = 0; j < 32; j += 4) {
            uint2 v0 = tab[sc[jb + j + 0] + hq];
            uint2 v1 = tab[sc[jb + j + 1] + hq];
            uint2 v2 = tab[sc[jb + j + 2] + hq];
            uint2 v3 = tab[sc[jb + j + 3] + hq];
            float2 a0 = __half22float2(*(__half2*)&v0.x), b0 = __half22float2(*(__half2*)&v0.y);
            float2 a1 = __half22float2(*(__half2*)&v1.x), b1 = __half22float2(*(__half2*)&v1.y);
            float2 a2 = __half22float2(*(__half2*)&v2.x), b2 = __half22float2(*(__half2*)&v2.y);
            float2 a3 = __half22float2(*(__half2*)&v3.x), b3 = __half22float2(*(__half2*)&v3.y);
            A0.x += a0.x; A0.y += a0.y; B0.x += b0.x; B0.y += b0.y;
            A1.x += a1.x; A1.y += a1.y; B1.x += b1.x; B1.y += b1.y;
            A2.x += a2.x; A2.y += a2.y; B2.x += b2.x; B2.y += b2.y;
            A3.x += a3.x; A3.y += a3.y; B3.x += b3.x; B3.y += b3.y;
        }
        part[sl][hq] = make_float4(A0.x + A1.x + A2.x + A3.x,
                                   A0.y + A1.y + A2.y + A3.y,
                                   B0.x + B1.x + B2.x + B3.x,
                                   B0.y + B1.y + B2.y + B3.y);
    }
    __syncthreads();
    if (t < 64) {
        float4 f = part[0][t];
        #pragma unroll
        for (int s = 1; s < 8; ++s) {
            float4 g = part[s][t];
            f.x += g.x; f.y += g.y; f.z += g.z; f.w += g.w;
        }
        atomicAdd(&g_mean[b * H + 4 * t + 0], f.x);
        atomicAdd(&g_mean[b * H + 4 * t + 1], f.y);
        atomicAdd(&g_mean[b * H + 4 * t + 2], f.z);
        atomicAdd(&g_mean[b * H + 4 * t + 3], f.w);
    }
    __syncthreads();

    {   // ligand: 4 atoms per thread
        float2 A0 = {0,0}, B0 = {0,0}, A1 = {0,0}, B1 = {0,0};
        int jb = sl * 4;
        #pragma unroll
        for (int j = 0; j < 4; j += 2) {
            uint2 v0 = ltab[scl[jb + j + 0] + hq];
            uint2 v1 = ltab[scl[jb + j + 1] + hq];
            float2 a0 = __half22float2(*(__half2*)&v0.x), b0 = __half22float2(*(__half2*)&v0.y);
            float2 a1 = __half22float2(*(__half2*)&v1.x), b1 = __half22float2(*(__half2*)&v1.y);
            A0.x += a0.x; A0.y += a0.y; B0.x += b0.x; B0.y += b0.y;
            A1.x += a1.x; A1.y += a1.y; B1.x += b1.x; B1.y += b1.y;
        }
        part[sl][hq] = make_float4(A0.x + A1.x, A0.y + A1.y, B0.x + B1.x, B0.y + B1.y);
    }
    __syncthreads();
    if (t < 64) {
        float4 f = part[0][t];
        #pragma unroll
        for (int s = 1; s < 8; ++s) {
            float4 g = part[s][t];
            f.x += g.x; f.y += g.y; f.z += g.z; f.w += g.w;
        }
        atomicAdd(&g_mean[BSZ * H + b * H + 4 * t + 0], f.x);
        atomicAdd(&g_mean[BSZ * H + b * H + 4 * t + 1], f.y);
        atomicAdd(&g_mean[BSZ * H + b * H + 4 * t + 2], f.z);
        atomicAdd(&g_mean[BSZ * H + b * H + 4 * t + 3], f.w);
    }
}

// ============================================================================
// K4 — 128 blocks x 512: (batch-OCTET x h-strip of 32). fp32 M, 8 batches
//      per M load. Thread = (h32 = t>>4, kc = t&15). Coalesced float4 loads,
//      width-16 shfl reduce, 8 warps x 1 batch epilogue, atomics -> out.
// ============================================================================
__global__ void __launch_bounds__(512)
k_head(const float* __restrict__ Wa1, const float* __restrict__ Wa2,
       const float* __restrict__ ba2, float* __restrict__ out) {
    __shared__ float smean[8][512];      // 16KB
    __shared__ float spart[32][8];       // [h32][batch]
    __shared__ float scont[8][2];
    int blk = blockIdx.x, t = threadIdx.x;
    int oct = blk >> 3, qh = blk & 7;    // batch octet, h-strip
    int b0 = oct * 8;
    int h32 = t >> 4, kc = t & 15;       // h within strip (32), k-chunk (16)
    int hg = qh * 32 + h32;              // global h

    // load means, scaled (8 per thread, coalesced)
    for (int i = t; i < 4096; i += 512) {
        int which = i >> 9, idx = i & 511;
        int b = b0 + which;
        float v = (idx < 256) ? g_mean[b * H + idx] * (1.0f / PPA)
                              : g_mean[BSZ * H + b * H + (idx - 256)] * (1.0f / LPA);
        smean[which][idx] = v;
    }

    // contact merge: 8 warps, one batch each; 4 lig atoms per lane
    if (t < 256) {
        int wb = t >> 5, lane = t & 31;
        int b = b0 + wb;
        float s = 0.f, mn = 3.4e38f;
        #pragma unroll
        for (int j = 0; j < 4; ++j) {
            int la = lane + j * 32;
            float m = fminf(g_lmin[(2 * b) * LPA + la], g_lmin[(2 * b + 1) * LPA + la]);
            float dist = sqrtf(fmaxf(m, 0.f));
            s += dist;
            mn = fminf(mn, dist);
        }
        #pragma unroll
        for (int o = 16; o > 0; o >>= 1) {
            s += __shfl_down_sync(0xffffffffu, s, o);
            mn = fminf(mn, __shfl_down_sync(0xffffffffu, mn, o));
        }
        if (lane == 0) {
            scont[wb][0] = s * (1.0f / LPA);
            scont[wb][1] = mn;
        }
    }
    __syncthreads();

    // GEMM: lane kc reads float4 i*16+kc of MT row hg (coalesced in 16-lane
    // groups); each float4 (4 k) feeds 8 batches.
    float acc[8] = {0.f, 0.f, 0.f, 0.f, 0.f, 0.f, 0.f, 0.f};
    {
        const float4* row = (const float4*)(g_MTf + hg * 512);
        #pragma unroll
        for (int i = 0; i < 8; ++i) {
            float4 w = row[i * 16 + kc];
            int k = (i * 16 + kc) * 4;
            #pragma unroll
            for (int b = 0; b < 8; ++b) {
                float4 s = *(const float4*)&smean[b][k];
                acc[b] += w.x * s.x + w.y * s.y + w.z * s.z + w.w * s.w;
            }
        }
        #pragma unroll
        for (int o = 8; o > 0; o >>= 1) {
            #pragma unroll
            for (int b = 0; b < 8; ++b)
                acc[b] += __shfl_down_sync(0xffffffffu, acc[b], o, 16);
        }
        if (kc == 0) {
            #pragma unroll
            for (int b = 0; b < 8; ++b) spart[h32][b] = acc[b];
        }
    }
    __syncthreads();

    // epilogue: 8 warps x 1 batch, 32 lanes = 32 h of this strip
    if (t < 256) {
        int wb = t >> 5, hi = t & 31;
        int hcol = qh * 32 + hi;
        float f = spart[hi][wb];
        float cv = g_cpart[0][hcol] + g_cpart[1][hcol] + g_cpart[2][hcol] + g_cpart[3][hcol];
        float c0 = scont[wb][0], c1 = scont[wb][1];
        float ax = f + cv + c0 * Wa1[512 * H + hcol] + c1 * Wa1[513 * H + hcol];
        float p = silu_acc(ax) * Wa2[hcol];
        #pragma unroll
        for (int o = 16; o > 0; o >>= 1) p += __shfl_down_sync(0xffffffffu, p, o);
        if ((t & 31) == 0) {
            float bias = (qh == 0) ? ba2[0] : 0.f;
            atomicAdd(&out[b0 + wb], p + bias);
        }
    }
}

extern "C" void kernel_launch(void* const* d_in, const int* in_sizes, int n_in,
                              void* d_out, int out_size) {
    const float* ppos   = (const float*)d_in[0];
    const float* lpos   = (const float*)d_in[1];
    const int*   pelem  = (const int*)d_in[2];
    const int*   paa    = (const int*)d_in[3];
    const int*   pbb    = (const int*)d_in[4];
    const int*   ltype  = (const int*)d_in[5];
    // d_in[6], d_in[7]: batch index arrays — contiguous, unused
    const float* E_elem = (const float*)d_in[8];
    const float* E_aa   = (const float*)d_in[9];
    const float* E_bb   = (const float*)d_in[10];
    const float* E_lig  = (const float*)d_in[11];
    const float* Wd1    = (const float*)d_in[12];
    const float* bd1    = (const float*)d_in[13];
    const float* Wd2    = (const float*)d_in[14];
    const float* bd2    = (const float*)d_in[15];
    const float* Wa1    = (const float*)d_in[16];
    const float* ba1    = (const float*)d_in[17];
    const float* Wa2    = (const float*)d_in[18];
    const float* ba2    = (const float*)d_in[19];
    float* out = (float*)d_out;

    k_embed<<<109, 512>>>(E_elem, E_aa, E_bb, E_lig, Wd1, out);
    k_big<<<388 + NCOMBO / 2 + 8, 256>>>(Wd2, Wa1, bd2, ba1, bd1, ppos, lpos);
    k_pool<<<512, 512>>>(pelem, paa, pbb, ltype);
    k_head<<<128, 512>>>(Wa1, Wa2, ba2, out);
}

// round 16
// speedup vs baseline: 1.1393x; 1.1393x over previous
#include <cuda_runtime.h>
#include <cuda_fp16.h>
#include <math.h>

#define H      256
#define BSZ    128
#define PPA    1024
#define LPA    128
#define NCOMBO 8192

// -------- scratch (no allocations allowed) --------
__device__ float4  g_F4[180 * (H / 4)];          // embed@Wd1 rows
#define G_F ((const float*)g_F4)
__device__ __half2 g_table_h2[NCOMBO * (H / 2)]; // fp16 silu table (4.2MB)
__device__ __half2 g_ligtab_h2[16 * (H / 2)];
__device__ __half2 g_M_h2[512 * (H / 2)];        // rows 0-255: Wd2@Wa1_P, 256-511: Wd2@Wa1_L
__device__ float   g_cpart[4][H];                // const-vector partials (bd2 fold + ba1)
__device__ float   g_lmin[BSZ * 2 * LPA];        // partial min d2 (+|l|^2) per (batch,half,atom)
__device__ float   g_mean[2 * BSZ * H];          // [0,32768): protein sums, [32768,): ligand sums

__device__ __forceinline__ float silu_acc(float x) {
    return x / (1.0f + expf(-x));
}
// Polynomial sigma for tiny |x| (table pre-acts ~N(0,0.011)); exact fallback.
__device__ __forceinline__ float silu_poly(float x) {
    float x2 = x * x;
    float s = 0.5f + x * (0.25f + x2 * (-1.0f / 48.0f + x2 * (1.0f / 480.0f)));
    if (fabsf(x) > 0.25f) s = __fdividef(1.0f, 1.0f + __expf(-x));
    return x * s;
}

__device__ __forceinline__ const float* emb_src(int r, const float* Ee, const float* Ea,
                                                const float* Eb, const float* El) {
    if (r < 128) return Ee + r * H;
    if (r < 160) return Ea + (r - 128) * H;
    if (r < 162) return Eb + (r - 160) * H;
    if (r < 178) return El + (r - 162) * H;
    return Ee;  // dummy rows
}

// ============================================================================
// K1 — 109 blocks x 512: [0,45) embed GEMM -> g_F; [45,109) zero g_mean (+out)
// ============================================================================
__global__ void __launch_bounds__(512)
k_embed(const float* __restrict__ E_elem, const float* __restrict__ E_aa,
        const float* __restrict__ E_bb,   const float* __restrict__ E_lig,
        const float* __restrict__ Wd1,    float* __restrict__ out) {
    __shared__ float  sA[4][H];
    __shared__ float4 sRed[8][4][64];
    int blk = blockIdx.x, t = threadIdx.x;
    if (blk >= 45) {
        ((float2*)g_mean)[(blk - 45) * 512 + t] = make_float2(0.f, 0.f);
        if (blk == 45 && t < BSZ) out[t] = 0.f;
        return;
    }
    int r0 = blk * 4;
    for (int r = t >> 8; r < 4; r += 2)
        sA[r][t & 255] = emb_src(r0 + r, E_elem, E_aa, E_bb, E_lig)[t & 255];
    __syncthreads();
    int q = t >> 6, u = t & 63;
    float4 a0 = {0,0,0,0}, a1 = {0,0,0,0}, a2 = {0,0,0,0}, a3 = {0,0,0,0};
    const float* Wp = Wd1 + (q * 32) * H + 4 * u;
    const float* sa = &sA[0][q * 32];
    #pragma unroll 8
    for (int j = 0; j < 32; ++j) {
        float4 w = *(const float4*)(Wp + j * H);
        float s0 = sa[0 * H + j], s1 = sa[1 * H + j];
        float s2 = sa[2 * H + j], s3 = sa[3 * H + j];
        a0.x += s0 * w.x; a0.y += s0 * w.y; a0.z += s0 * w.z; a0.w += s0 * w.w;
        a1.x += s1 * w.x; a1.y += s1 * w.y; a1.z += s1 * w.z; a1.w += s1 * w.w;
        a2.x += s2 * w.x; a2.y += s2 * w.y; a2.z += s2 * w.z; a2.w += s2 * w.w;
        a3.x += s3 * w.x; a3.y += s3 * w.y; a3.z += s3 * w.z; a3.w += s3 * w.w;
    }
    sRed[q][0][u] = a0; sRed[q][1][u] = a1;
    sRed[q][2][u] = a2; sRed[q][3][u] = a3;
    __syncthreads();
    if (t < 256) {
        int r = t >> 6, u2 = t & 63;
        float4 f = sRed[0][r][u2];
        #pragma unroll
        for (int q2 = 1; q2 < 8; ++q2) {
            float4 g = sRed[q2][r][u2];
            f.x += g.x; f.y += g.y; f.z += g.z; f.w += g.w;
        }
        g_F4[(r0 + r) * (H / 4) + u2] = f;
    }
}

// ============================================================================
// K2 — 4492 blocks x 256 (long blocks first):
//   [0,128) M GEMM; [128,132) const partials; [132,388) distance; rest tables
// ============================================================================
__global__ void __launch_bounds__(256)
k_big(const float* __restrict__ Wd2, const float* __restrict__ Wa1,
      const float* __restrict__ bd2, const float* __restrict__ ba1,
      const float* __restrict__ bd1,
      const float* __restrict__ ppos, const float* __restrict__ lpos) {
    __shared__ float  sA[4][H];
    __shared__ float4 sRed[4][4][64];
    __shared__ float4 sp[512];
    __shared__ float  dmin2[256];
    int blk = blockIdx.x, t = threadIdx.x;

    if (blk < 128) {
        // ---------------- M GEMM ----------------
        int r0 = blk * 4;
        #pragma unroll
        for (int r = 0; r < 4; ++r)
            sA[r][t] = Wd2[((r0 + r) & 255) * H + t];
        const float* W = Wa1 + ((r0 >> 8) * 256) * H;
        __syncthreads();
        int q = t >> 6, u = t & 63;
        float4 a0 = {0,0,0,0}, a1 = {0,0,0,0}, a2 = {0,0,0,0}, a3 = {0,0,0,0};
        const float* Wp = W + (q * 64) * H + 4 * u;
        const float* sa = &sA[0][q * 64];
        #pragma unroll 8
        for (int j = 0; j < 64; ++j) {
            float4 w = *(const float4*)(Wp + j * H);
            float s0 = sa[0 * H + j], s1 = sa[1 * H + j];
            float s2 = sa[2 * H + j], s3 = sa[3 * H + j];
            a0.x += s0 * w.x; a0.y += s0 * w.y; a0.z += s0 * w.z; a0.w += s0 * w.w;
            a1.x += s1 * w.x; a1.y += s1 * w.y; a1.z += s1 * w.z; a1.w += s1 * w.w;
            a2.x += s2 * w.x; a2.y += s2 * w.y; a2.z += s2 * w.z; a2.w += s2 * w.w;
            a3.x += s3 * w.x; a3.y += s3 * w.y; a3.z += s3 * w.z; a3.w += s3 * w.w;
        }
        sRed[q][0][u] = a0; sRed[q][1][u] = a1;
        sRed[q][2][u] = a2; sRed[q][3][u] = a3;
        __syncthreads();
        int r = t >> 6, u2 = t & 63;
        float4 f0 = sRed[0][r][u2], f1 = sRed[1][r][u2];
        float4 f2 = sRed[2][r][u2], f3 = sRed[3][r][u2];
        float4 f = make_float4(f0.x + f1.x + f2.x + f3.x,
                               f0.y + f1.y + f2.y + f3.y,
                               f0.z + f1.z + f2.z + f3.z,
                               f0.w + f1.w + f2.w + f3.w);
        g_M_h2[(r0 + r) * (H / 2) + 2 * u2 + 0] = __floats2half2_rn(f.x, f.y);
        g_M_h2[(r0 + r) * (H / 2) + 2 * u2 + 1] = __floats2half2_rn(f.z, f.w);
    } else if (blk < 132) {
        // ---------------- const partials ----------------
        int qq = blk - 128;
        int j0 = qq * 64;
        float acc = (qq == 0) ? ba1[t] : 0.f;
        #pragma unroll 8
        for (int j = j0; j < j0 + 64; ++j) {
            float b = bd2[j];
            acc += b * (Wa1[j * H + t] + Wa1[(256 + j) * H + t]);
        }
        g_cpart[qq][t] = acc;
    } else if (blk < 388) {
        // ---------------- distance partial min ----------------
        int d = blk - 132;
        int b = d >> 1, half = d & 1;
        for (int j = t; j < 512; j += 256) {
            int i = b * PPA + half * 512 + j;
            float px = ppos[3 * i], py = ppos[3 * i + 1], pz = ppos[3 * i + 2];
            sp[j] = make_float4(px, py, pz, px * px + py * py + pz * pz);
        }
        __syncthreads();
        int la = t & 127, jh = t >> 7;
        int li = b * LPA + la;
        float lx = lpos[3 * li], ly = lpos[3 * li + 1], lz = lpos[3 * li + 2];
        float ll = lx * lx + ly * ly + lz * lz;
        float nx = -2.f * lx, ny = -2.f * ly, nz = -2.f * lz;
        float b0 = 3.4e38f, b1 = 3.4e38f;
        int base = jh * 256;
        #pragma unroll 4
        for (int j = 0; j < 256; j += 2) {
            float4 p  = sp[base + j];
            float4 q4 = sp[base + j + 1];
            float d0 = fmaf(nx, p.x,  fmaf(ny, p.y,  fmaf(nz, p.z,  p.w)));
            float d1 = fmaf(nx, q4.x, fmaf(ny, q4.y, fmaf(nz, q4.z, q4.w)));
            b0 = fminf(b0, d0);
            b1 = fminf(b1, d1);
        }
        dmin2[t] = fminf(b0, b1);
        __syncthreads();
        if (t < 128)
            g_lmin[d * LPA + t] = fminf(dmin2[t], dmin2[t + 128]) + ll;
    } else {
        // ---------------- silu tables ----------------
        int tb = blk - 388;
        int hp = t & 127;
        if (tb < NCOMBO / 2) {
            int c = 2 * tb + (t >> 7);
            int e = c >> 6, a = (c >> 1) & 31, bbn = c & 1;
            float2 fe = *(const float2*)&G_F[e * H + 2 * hp];
            float2 fa = *(const float2*)&G_F[(128 + a) * H + 2 * hp];
            float2 fb = *(const float2*)&G_F[(160 + bbn) * H + 2 * hp];
            float2 bd = *(const float2*)&bd1[2 * hp];
            g_table_h2[c * (H / 2) + hp] =
                __floats2half2_rn(silu_poly(fe.x + fa.x + fb.x + bd.x),
                                  silu_poly(fe.y + fa.y + fb.y + bd.y));
        } else {
            int c = 2 * (tb - NCOMBO / 2) + (t >> 7);
            float2 fl = *(const float2*)&G_F[(162 + c) * H + 2 * hp];
            float2 bd = *(const float2*)&bd1[2 * hp];
            g_ligtab_h2[c * (H / 2) + hp] =
                __floats2half2_rn(silu_poly(fl.x + bd.x), silu_poly(fl.y + bd.y));
        }
    }
}

// ============================================================================
// K3 — 256 blocks x 1024 (2 blocks/batch), uint2 gathers, HADD2 4-atom trees
// ============================================================================
__global__ void __launch_bounds__(1024)
k_pool(const int* __restrict__ elem, const int* __restrict__ aa,
       const int* __restrict__ bb,   const int* __restrict__ ltype) {
    __shared__ int    sc[512];
    __shared__ int    scl[64];
    __shared__ float4 part[16][64];
    int d = blockIdx.x, t = threadIdx.x;
    int b = d >> 1, half = d & 1;
    int hq = t & 63, sl = t >> 6;
    const uint2* tab = (const uint2*)g_table_h2;
    const uint2* ltab = (const uint2*)g_ligtab_h2;

    if (t < 512) {
        int i = b * PPA + half * 512 + t;
        sc[t] = ((elem[i] << 6) | (aa[i] << 1) | bb[i]) << 6;
    } else if (t < 576) {
        scl[t - 512] = ltype[b * LPA + half * 64 + (t - 512)] << 6;
    }
    __syncthreads();

    {   // protein: 32 atoms per thread; fp16 pairwise sums over 4-atom groups
        float2 A = {0.f, 0.f}, B = {0.f, 0.f};
        float2 A2 = {0.f, 0.f}, B2 = {0.f, 0.f};
        int jb = sl * 32;
        #pragma unroll 4
        for (int j = 0; j < 32; j += 8) {
            uint2 v0 = tab[sc[jb + j + 0] + hq];
            uint2 v1 = tab[sc[jb + j + 1] + hq];
            uint2 v2 = tab[sc[jb + j + 2] + hq];
            uint2 v3 = tab[sc[jb + j + 3] + hq];
            uint2 v4 = tab[sc[jb + j + 4] + hq];
            uint2 v5 = tab[sc[jb + j + 5] + hq];
            uint2 v6 = tab[sc[jb + j + 6] + hq];
            uint2 v7 = tab[sc[jb + j + 7] + hq];
            __half2 lo0 = __hadd2(__hadd2(*(__half2*)&v0.x, *(__half2*)&v1.x),
                                  __hadd2(*(__half2*)&v2.x, *(__half2*)&v3.x));
            __half2 hi0 = __hadd2(__hadd2(*(__half2*)&v0.y, *(__half2*)&v1.y),
                                  __hadd2(*(__half2*)&v2.y, *(__half2*)&v3.y));
            __half2 lo1 = __hadd2(__hadd2(*(__half2*)&v4.x, *(__half2*)&v5.x),
                                  __hadd2(*(__half2*)&v6.x, *(__half2*)&v7.x));
            __half2 hi1 = __hadd2(__hadd2(*(__half2*)&v4.y, *(__half2*)&v5.y),
                                  __hadd2(*(__half2*)&v6.y, *(__half2*)&v7.y));
            float2 f0 = __half22float2(lo0), g0 = __half22float2(hi0);
            float2 f1 = __half22float2(lo1), g1 = __half22float2(hi1);
            A.x  += f0.x; A.y  += f0.y; B.x  += g0.x; B.y  += g0.y;
            A2.x += f1.x; A2.y += f1.y; B2.x += g1.x; B2.y += g1.y;
        }
        part[sl][hq] = make_float4(A.x + A2.x, A.y + A2.y, B.x + B2.x, B.y + B2.y);
    }
    __syncthreads();
    if (t < 64) {
        float4 f = part[0][t];
        #pragma unroll
        for (int s = 1; s < 16; ++s) {
            float4 g = part[s][t];
            f.x += g.x; f.y += g.y; f.z += g.z; f.w += g.w;
        }
        atomicAdd(&g_mean[b * H + 4 * t + 0], f.x);
        atomicAdd(&g_mean[b * H + 4 * t + 1], f.y);
        atomicAdd(&g_mean[b * H + 4 * t + 2], f.z);
        atomicAdd(&g_mean[b * H + 4 * t + 3], f.w);
    }
    __syncthreads();

    {   // ligand: 4 atoms per thread (fp16 tree then fp32)
        int jb = sl * 4;
        uint2 v0 = ltab[scl[jb + 0] + hq];
        uint2 v1 = ltab[scl[jb + 1] + hq];
        uint2 v2 = ltab[scl[jb + 2] + hq];
        uint2 v3 = ltab[scl[jb + 3] + hq];
        __half2 lo = __hadd2(__hadd2(*(__half2*)&v0.x, *(__half2*)&v1.x),
                             __hadd2(*(__half2*)&v2.x, *(__half2*)&v3.x));
        __half2 hi = __hadd2(__hadd2(*(__half2*)&v0.y, *(__half2*)&v1.y),
                             __hadd2(*(__half2*)&v2.y, *(__half2*)&v3.y));
        float2 flo = __half22float2(lo);
        float2 fhi = __half22float2(hi);
        part[sl][hq] = make_float4(flo.x, flo.y, fhi.x, fhi.y);
    }
    __syncthreads();
    if (t < 64) {
        float4 f = part[0][t];
        #pragma unroll
        for (int s = 1; s < 16; ++s) {
            float4 g = part[s][t];
            f.x += g.x; f.y += g.y; f.z += g.z; f.w += g.w;
        }
        atomicAdd(&g_mean[BSZ * H + b * H + 4 * t + 0], f.x);
        atomicAdd(&g_mean[BSZ * H + b * H + 4 * t + 1], f.y);
        atomicAdd(&g_mean[BSZ * H + b * H + 4 * t + 2], f.z);
        atomicAdd(&g_mean[BSZ * H + b * H + 4 * t + 3], f.w);
    }
}

// ============================================================================
// K4 — 128 blocks x 1024: (batch-pair x h-half). Contact merge + head partials,
//      h-half partial sums atomically combined into out[b] (zero-initialized).
//      (Exact structure of the verified 33.2us kernel.)
// ============================================================================
__global__ void __launch_bounds__(1024)
k_head(const float* __restrict__ Wa1, const float* __restrict__ Wa2,
       const float* __restrict__ ba2, float* __restrict__ out) {
    __shared__ float  smean[2][512];
    __shared__ float4 part[16][64];
    __shared__ float  rws[2][4], rwm[2][4], rw[8];
    __shared__ float  scont[2][2];
    int blk = blockIdx.x, t = threadIdx.x;
    int pair = blk >> 1, hh = blk & 1;
    int b0 = pair * 2;
    int hq = t & 63, sl = t >> 6;
    int hp = hh * 64 + hq;              // half2 column index

    {   // load means, scaled
        int which = t >> 9, idx = t & 511;
        int b = b0 + which;
        float v = (idx < 256) ? g_mean[b * H + idx] * (1.0f / PPA)
                              : g_mean[BSZ * H + b * H + (idx - 256)] * (1.0f / LPA);
        smean[which][idx] = v;
    }

    // contact merge: warps 0-3 batch0, warps 4-7 batch1
    if (t < 256) {
        int which = t >> 7, la = t & 127;
        int b = b0 + which;
        float m = fminf(g_lmin[(2 * b) * LPA + la], g_lmin[(2 * b + 1) * LPA + la]);
        float dist = sqrtf(fmaxf(m, 0.f));
        float s = dist, mn = dist;
        #pragma unroll
        for (int o = 16; o > 0; o >>= 1) {
            s += __shfl_down_sync(0xffffffffu, s, o);
            mn = fminf(mn, __shfl_down_sync(0xffffffffu, mn, o));
        }
        if ((la & 31) == 0) { rws[which][la >> 5] = s; rwm[which][la >> 5] = mn; }
    }
    __syncthreads();
    if (t < 2) {
        scont[t][0] = (rws[t][0] + rws[t][1] + rws[t][2] + rws[t][3]) * (1.0f / LPA);
        scont[t][1] = fminf(fminf(rwm[t][0], rwm[t][1]), fminf(rwm[t][2], rwm[t][3]));
    }
    __syncthreads();

    // head GEMM: 32 k per thread over combined [P;L] (512 k)
    {
        float2 acc0 = {0.f, 0.f}, acc1 = {0.f, 0.f};
        int koff = sl * 32;
        #pragma unroll 8
        for (int k = 0; k < 32; ++k) {
            int kk = koff + k;
            float2 w = __half22float2(g_M_h2[kk * (H / 2) + hp]);
            float m0 = smean[0][kk], m1 = smean[1][kk];
            acc0.x += m0 * w.x; acc0.y += m0 * w.y;
            acc1.x += m1 * w.x; acc1.y += m1 * w.y;
        }
        part[sl][hq] = make_float4(acc0.x, acc0.y, acc1.x, acc1.y);
    }
    __syncthreads();

    if (t < 128) {
        int which = t >> 6, q = t & 63;   // batch, h-quad
        float4 f = part[0][q];
        #pragma unroll
        for (int s = 1; s < 16; ++s) {
            float4 g = part[s][q];
            f.x += g.x; f.y += g.y; f.z += g.z; f.w += g.w;
        }
        float fx = which ? f.z : f.x;
        float fy = which ? f.w : f.y;
        int hcol = hh * 64 + q;
        int h0 = 2 * hcol, h1 = 2 * hcol + 1;
        float cv0 = g_cpart[0][h0] + g_cpart[1][h0] + g_cpart[2][h0] + g_cpart[3][h0];
        float cv1 = g_cpart[0][h1] + g_cpart[1][h1] + g_cpart[2][h1] + g_cpart[3][h1];
        float c0 = scont[which][0], c1 = scont[which][1];
        float ax = fx + cv0 + c0 * Wa1[512 * H + h0] + c1 * Wa1[513 * H + h0];
        float ay = fy + cv1 + c0 * Wa1[512 * H + h1] + c1 * Wa1[513 * H + h1];
        float p = silu_acc(ax) * Wa2[h0] + silu_acc(ay) * Wa2[h1];
        #pragma unroll
        for (int o = 16; o > 0; o >>= 1) p += __shfl_down_sync(0xffffffffu, p, o);
        if ((t & 31) == 0) rw[t >> 5] = p;
    }
    __syncthreads();
    if (t == 0) {
        float bias = (hh == 0) ? ba2[0] : 0.f;
        atomicAdd(&out[b0 + 0], rw[0] + rw[1] + bias);
        atomicAdd(&out[b0 + 1], rw[2] + rw[3] + ((hh == 0) ? ba2[0] : 0.f));
    }
}

extern "C" void kernel_launch(void* const* d_in, const int* in_sizes, int n_in,
                              void* d_out, int out_size) {
    const float* ppos   = (const float*)d_in[0];
    const float* lpos   = (const float*)d_in[1];
    const int*   pelem  = (const int*)d_in[2];
    const int*   paa    = (const int*)d_in[3];
    const int*   pbb    = (const int*)d_in[4];
    const int*   ltype  = (const int*)d_in[5];
    // d_in[6], d_in[7]: batch index arrays — contiguous, unused
    const float* E_elem = (const float*)d_in[8];
    const float* E_aa   = (const float*)d_in[9];
    const float* E_bb   = (const float*)d_in[10];
    const float* E_lig  = (const float*)d_in[11];
    const float* Wd1    = (const float*)d_in[12];
    const float* bd1    = (const float*)d_in[13];
    const float* Wd2    = (const float*)d_in[14];
    const float* bd2    = (const float*)d_in[15];
    const float* Wa1    = (const float*)d_in[16];
    const float* ba1    = (const float*)d_in[17];
    const float* Wa2    = (const float*)d_in[18];
    const float* ba2    = (const float*)d_in[19];
    float* out = (float*)d_out;

    k_embed<<<109, 512>>>(E_elem, E_aa, E_bb, E_lig, Wd1, out);
    k_big<<<388 + NCOMBO / 2 + 8, 256>>>(Wd2, Wa1, bd2, ba1, bd1, ppos, lpos);
    k_pool<<<2 * BSZ, 1024>>>(pelem, paa, pbb, ltype);
    k_head<<<BSZ, 1024>>>(Wa1, Wa2, ba2, out);
}